// round 13
// baseline (speedup 1.0000x reference)
#include <cuda_runtime.h>
#include <cuda_fp16.h>

#define N_ROWS 16384
#define DIM    512
#define NNZ_E  163840
#define ITERS  10

#define NBLK   888                 // single wave at 6 blocks/SM x 148 SMs
#define TPB    256
#define NWARP  (NBLK * 8)          // 7104 worker warps
#define HR_TOTAL (N_ROWS * 2)      // 32768 half-rows
#define W_FIX  3                   // fixed weight per half-row

// Scratch (static __device__ arrays — allocation-free per harness rules)
__device__ __align__(16) __half g_h0[N_ROWS * DIM];
__device__ __align__(16) __half g_h1[N_ROWS * DIM];
__device__ __align__(16) __half g_xh[N_ROWS * DIM];   // fp16 shadow of x
__device__ __align__(16) __half g_cx[N_ROWS * DIM];   // fp16 x*b*invdenom (written by iter 0)
__device__ int2  g_cw[NNZ_E];          // (col*DIM element offset, half2(sup,sup))
__device__ int   g_rowptr[N_ROWS + 1];
__device__ int   g_wsplit[NWARP + 1];  // balanced half-row ranges per warp
__device__ float g_invnorm[N_ROWS];
__device__ float g_rowsum[N_ROWS];
__device__ float g_aidn[N_ROWS];
__device__ float g_idn[N_ROWS];
__device__ float g_scal[3];            // a, b, k = 1/(4 s^2)

// ---------------------------------------------------------------------------
// warp per row: inv L2 norm + fp16 shadow; spare threads: CSR rowptr + scalars
__global__ void k_invnorm(const float* __restrict__ x,
                          const int*   __restrict__ er,
                          const float* __restrict__ alpha,
                          const float* __restrict__ beta,
                          const float* __restrict__ sigma) {
    int t    = blockIdx.x * blockDim.x + threadIdx.x;
    int row  = t >> 5;
    int lane = t & 31;

    if (t == N_ROWS + 1) {                 // one spare thread: scalars
        float a = expf(alpha[0]);
        float b = expf(beta[0]);
        float s = expf(sigma[0]);
        g_scal[0] = a;
        g_scal[1] = b;
        g_scal[2] = 1.0f / (4.0f * s * s);
    }
    if (t <= N_ROWS) {                     // fused rowptr lower_bound
        int lo = 0, hi = NNZ_E;
        while (lo < hi) {
            int mid = (lo + hi) >> 1;
            if (er[mid] < t) lo = mid + 1; else hi = mid;
        }
        g_rowptr[t] = lo;
    }
    if (row >= N_ROWS) return;

    const float4* xr = (const float4*)(x + (size_t)row * DIM);
    uint4* xh = (uint4*)(g_xh + (size_t)row * DIM);

    float s = 0.0f;
#pragma unroll
    for (int seg = 0; seg < 2; seg++) {
        float4 a = xr[2 * lane + 64 * seg];
        float4 b = xr[2 * lane + 1 + 64 * seg];
        s += a.x * a.x + a.y * a.y + a.z * a.z + a.w * a.w;
        s += b.x * b.x + b.y * b.y + b.z * b.z + b.w * b.w;
        __half2 h0 = __floats2half2_rn(a.x, a.y);
        __half2 h1 = __floats2half2_rn(a.z, a.w);
        __half2 h2 = __floats2half2_rn(b.x, b.y);
        __half2 h3 = __floats2half2_rn(b.z, b.w);
        uint4 u;
        u.x = *(unsigned*)&h0; u.y = *(unsigned*)&h1;
        u.z = *(unsigned*)&h2; u.w = *(unsigned*)&h3;
        xh[lane + 32 * seg] = u;
    }
#pragma unroll
    for (int o = 16; o; o >>= 1) s += __shfl_xor_sync(0xFFFFFFFFu, s, o);
    if (lane == 0) {
        g_invnorm[row] = rsqrtf(fmaxf(s, 1e-12f));
        g_rowsum[row]  = 0.0f;
    }
}

// 8 lanes per edge (4 edges/warp): 16 indep loads in flight per lane.
// Writes (col*DIM, half2(sup,sup)) so the iter loop needs zero conversions.
__global__ void k_sup(const float* __restrict__ ev,
                      const int*   __restrict__ er,
                      const int*   __restrict__ ec) {
    int t = blockIdx.x * blockDim.x + threadIdx.x;
    int e = t >> 3;
    int q = t & 7;
    if (e >= NNZ_E) return;

    int row = er[e];
    int col = ec[e];
    const uint4* xr = (const uint4*)(g_xh + (size_t)row * DIM);
    const uint4* xc = (const uint4*)(g_xh + (size_t)col * DIM);

    __half2 acc0 = __float2half2_rn(0.0f);
    __half2 acc1 = __float2half2_rn(0.0f);
#pragma unroll
    for (int j = 0; j < 8; j += 2) {
        uint4 r0 = xr[q + 8 * j];
        uint4 c0 = xc[q + 8 * j];
        uint4 r1 = xr[q + 8 * (j + 1)];
        uint4 c1 = xc[q + 8 * (j + 1)];
#pragma unroll
        for (int m = 0; m < 4; m++) {
            unsigned ra = (&r0.x)[m], ca = (&c0.x)[m];
            unsigned rb = (&r1.x)[m], cb = (&c1.x)[m];
            acc0 = __hfma2(*(__half2*)&ra, *(__half2*)&ca, acc0);
            acc1 = __hfma2(*(__half2*)&rb, *(__half2*)&cb, acc1);
        }
    }
    float2 f0 = __half22float2(acc0);
    float2 f1 = __half22float2(acc1);
    float d = f0.x + f0.y + f1.x + f1.y;
    d += __shfl_xor_sync(0xFFFFFFFFu, d, 1);
    d += __shfl_xor_sync(0xFFFFFFFFu, d, 2);
    d += __shfl_xor_sync(0xFFFFFFFFu, d, 4);

    if (q == 0) {
        float sim = (col == row) ? 0.0f : d * g_invnorm[row] * g_invnorm[col];
        float sup = ev[e] * expf(sim * g_scal[2]);
        __half2 wh = __float2half2_rn(sup);
        g_cw[e] = make_int2(col << 9, *(int*)&wh);
        atomicAdd(&g_rowsum[row], sup);
    }
}

// cumulative weight up to (but not including) half-row hr
__device__ __forceinline__ long long cumW(int hr) {
    int r = hr >> 1, h = hr & 1;
    long long edges = 2LL * g_rowptr[r] + (h ? (g_rowptr[r + 1] - g_rowptr[r]) : 0);
    return edges + (long long)W_FIX * hr;
}

// tiny: denom arrays (per row) + balanced warp splits (per warp slot)
__global__ void k_meta() {
    int i = blockIdx.x * blockDim.x + threadIdx.x;
    float a = g_scal[0], b = g_scal[1];

    if (i < N_ROWS) {
        float idn = 1.0f / (b + g_rowsum[i] * a + a);
        g_idn[i]  = idn;
        g_aidn[i] = a * idn;
    }
    if (i <= NWARP) {
        long long W = 2LL * NNZ_E + (long long)W_FIX * HR_TOTAL;
        long long tgt = (long long)i * W / NWARP;
        int lo = 0, hi = HR_TOTAL;
        while (lo < hi) {
            int mid = (lo + hi) >> 1;
            if (cumW(mid) < tgt) lo = mid + 1; else hi = mid;
        }
        g_wsplit[i] = lo;
    }
}

// balanced warps: each warp processes its half-row range for one iteration.
// 4-edge groups (R11-proven width): half2 chain (1 HMUL2 + 3 HFMA2 per word),
// one fp32 flush per word. Metadata is pre-shifted / pre-converted by k_sup.
__global__ void __launch_bounds__(TPB, 6)
k_iter(const __half* __restrict__ in_h,
       const float*  __restrict__ x,
       __half*       __restrict__ out_h,
       float*        __restrict__ out_f,
       int first, int last) {
    int gw   = (blockIdx.x * TPB + threadIdx.x) >> 5;
    int lane = threadIdx.x & 31;
    int hr0 = g_wsplit[gw];
    int hr1 = g_wsplit[gw + 1];

    for (int hr = hr0; hr < hr1; hr++) {
        int row = hr >> 1, half = hr & 1;
        int e0 = g_rowptr[row], e1 = g_rowptr[row + 1];
        float aidn = g_aidn[row];
        const __half* base = in_h + half * (DIM / 2);

        float acc[8];
#pragma unroll
        for (int i = 0; i < 8; i++) acc[i] = 0.0f;

        int e = e0;
        for (; e + 3 < e1; e += 4) {
            int2 A = g_cw[e], B = g_cw[e + 1], C = g_cw[e + 2], D = g_cw[e + 3];
            uint4 uA = ((const uint4*)(base + (unsigned)A.x))[lane];
            uint4 uB = ((const uint4*)(base + (unsigned)B.x))[lane];
            uint4 uC = ((const uint4*)(base + (unsigned)C.x))[lane];
            uint4 uD = ((const uint4*)(base + (unsigned)D.x))[lane];
            __half2 wA = *(__half2*)&A.y, wB = *(__half2*)&B.y;
            __half2 wC = *(__half2*)&C.y, wD = *(__half2*)&D.y;
#pragma unroll
            for (int j = 0; j < 4; j++) {
                unsigned ra = (&uA.x)[j], rb = (&uB.x)[j];
                unsigned rc = (&uC.x)[j], rd = (&uD.x)[j];
                __half2 t = __hmul2(wD, *(__half2*)&rd);
                t = __hfma2(wC, *(__half2*)&rc, t);
                t = __hfma2(wB, *(__half2*)&rb, t);
                t = __hfma2(wA, *(__half2*)&ra, t);
                float2 f = __half22float2(t);
                acc[2 * j]     += f.x;
                acc[2 * j + 1] += f.y;
            }
        }
        for (; e < e1; e++) {
            int2 A = g_cw[e];
            float w = __half2float(*(__half*)&A.y);
            uint4 u = ((const uint4*)(base + (unsigned)A.x))[lane];
#pragma unroll
            for (int j = 0; j < 4; j++) {
                unsigned raw = (&u.x)[j];
                float2 f = __half22float2(*(__half2*)&raw);
                acc[2 * j]     += w * f.x;
                acc[2 * j + 1] += w * f.y;
            }
        }

        size_t off = ((size_t)row << 9) + half * (DIM / 2);
        uint4 ui = ((const uint4*)(in_h + off))[lane];
        float fi[8];
#pragma unroll
        for (int j = 0; j < 4; j++) {
            unsigned raw = (&ui.x)[j];
            float2 f = __half22float2(*(__half2*)&raw);
            fi[2 * j] = f.x; fi[2 * j + 1] = f.y;
        }

        if (first) {
            // iter 0: fi == xh; forcing term computed inline, persisted to g_cx
            float sc = g_scal[1] * g_idn[row];
            float cx[8], o[8];
#pragma unroll
            for (int j = 0; j < 8; j++) {
                cx[j] = fi[j] * sc;
                o[j]  = cx[j] + (acc[j] + fi[j]) * aidn;
            }
            __half2 c0 = __floats2half2_rn(cx[0], cx[1]);
            __half2 c1 = __floats2half2_rn(cx[2], cx[3]);
            __half2 c2 = __floats2half2_rn(cx[4], cx[5]);
            __half2 c3 = __floats2half2_rn(cx[6], cx[7]);
            uint4 uc;
            uc.x = *(unsigned*)&c0; uc.y = *(unsigned*)&c1;
            uc.z = *(unsigned*)&c2; uc.w = *(unsigned*)&c3;
            ((uint4*)(g_cx + off))[lane] = uc;

            __half2 h0 = __floats2half2_rn(o[0], o[1]);
            __half2 h1 = __floats2half2_rn(o[2], o[3]);
            __half2 h2 = __floats2half2_rn(o[4], o[5]);
            __half2 h3 = __floats2half2_rn(o[6], o[7]);
            uint4 u;
            u.x = *(unsigned*)&h0; u.y = *(unsigned*)&h1;
            u.z = *(unsigned*)&h2; u.w = *(unsigned*)&h3;
            ((uint4*)(out_h + off))[lane] = u;
        } else if (!last) {
            uint4 uc = ((const uint4*)(g_cx + off))[lane];
            float o[8];
#pragma unroll
            for (int j = 0; j < 4; j++) {
                unsigned raw = (&uc.x)[j];
                float2 c = __half22float2(*(__half2*)&raw);
                o[2 * j]     = c.x + (acc[2 * j]     + fi[2 * j])     * aidn;
                o[2 * j + 1] = c.y + (acc[2 * j + 1] + fi[2 * j + 1]) * aidn;
            }
            __half2 h0 = __floats2half2_rn(o[0], o[1]);
            __half2 h1 = __floats2half2_rn(o[2], o[3]);
            __half2 h2 = __floats2half2_rn(o[4], o[5]);
            __half2 h3 = __floats2half2_rn(o[6], o[7]);
            uint4 u;
            u.x = *(unsigned*)&h0; u.y = *(unsigned*)&h1;
            u.z = *(unsigned*)&h2; u.w = *(unsigned*)&h3;
            ((uint4*)(out_h + off))[lane] = u;
        } else {
            float b = g_scal[1];
            float idn = g_idn[row];
            const float4* px = (const float4*)(x + off);
            float4 vx0 = px[2 * lane];
            float4 vx1 = px[2 * lane + 1];
            float4 o0, o1;
            o0.x = vx0.x * b * idn + (acc[0] + fi[0]) * aidn;
            o0.y = vx0.y * b * idn + (acc[1] + fi[1]) * aidn;
            o0.z = vx0.z * b * idn + (acc[2] + fi[2]) * aidn;
            o0.w = vx0.w * b * idn + (acc[3] + fi[3]) * aidn;
            o1.x = vx1.x * b * idn + (acc[4] + fi[4]) * aidn;
            o1.y = vx1.y * b * idn + (acc[5] + fi[5]) * aidn;
            o1.z = vx1.z * b * idn + (acc[6] + fi[6]) * aidn;
            o1.w = vx1.w * b * idn + (acc[7] + fi[7]) * aidn;
            float4* po = (float4*)(out_f + off);
            po[2 * lane]     = o0;
            po[2 * lane + 1] = o1;
        }
    }
}

// ---------------------------------------------------------------------------
extern "C" void kernel_launch(void* const* d_in, const int* in_sizes, int n_in,
                              void* d_out, int out_size) {
    const float* x     = (const float*)d_in[0];
    const float* alpha = (const float*)d_in[1];
    const float* beta  = (const float*)d_in[2];
    const float* sigma = (const float*)d_in[3];
    const float* ev    = (const float*)d_in[4];
    const int*   er    = (const int*)d_in[5];
    const int*   ec    = (const int*)d_in[6];
    float*       out   = (float*)d_out;

    __half *h0, *h1, *xh;
    cudaGetSymbolAddress((void**)&h0, g_h0);
    cudaGetSymbolAddress((void**)&h1, g_h1);
    cudaGetSymbolAddress((void**)&xh, g_xh);

    const int ROW_BLOCKS  = (N_ROWS * 32) / TPB;      // warp per row
    const int SUP_BLOCKS  = (NNZ_E * 8) / TPB;        // 8 threads per edge
    const int META_BLOCKS = (N_ROWS + TPB - 1) / TPB;

    k_invnorm<<<ROW_BLOCKS, TPB>>>(x, er, alpha, beta, sigma);
    k_sup<<<SUP_BLOCKS, TPB>>>(ev, er, ec);
    k_meta<<<META_BLOCKS, TPB>>>();

    const __half* in_h = xh;
    for (int it = 0; it < ITERS; it++) {
        int first = (it == 0);
        int last  = (it == ITERS - 1);
        __half* out_h = (it & 1) == 0 ? h0 : h1;
        k_iter<<<NBLK, TPB>>>(in_h, x, out_h, out, first, last);
        in_h = out_h;
    }
}

// round 14
// speedup vs baseline: 1.1074x; 1.1074x over previous
#include <cuda_runtime.h>
#include <cuda_fp16.h>

#define N_ROWS 16384
#define DIM    512
#define NNZ_E  163840
#define ITERS  10

#define NBLK   888                 // single wave at 6 blocks/SM x 148 SMs
#define TPB    256
#define NWARP  (NBLK * 8)          // 7104 worker warps
#define HR_TOTAL (N_ROWS * 2)      // 32768 half-rows
#define W_FIX  3                   // fixed weight per half-row

// Scratch (static __device__ arrays — allocation-free per harness rules)
__device__ __align__(16) __half g_h0[N_ROWS * DIM];
__device__ __align__(16) __half g_h1[N_ROWS * DIM];
__device__ __align__(16) __half g_xh[N_ROWS * DIM];   // fp16 shadow of x
__device__ __align__(16) __half g_cx[N_ROWS * DIM];   // fp16 x*b*invdenom (written by iter 0)
__device__ int2  g_cw[NNZ_E];          // (col, weight-as-int) per edge
__device__ int   g_rowptr[N_ROWS + 1];
__device__ int   g_wsplit[NWARP + 1];  // balanced half-row ranges per warp
__device__ float g_invnorm[N_ROWS];
__device__ float g_rowsum[N_ROWS];
__device__ float g_aidn[N_ROWS];
__device__ float g_idn[N_ROWS];
__device__ float g_scal[3];            // a, b, k = 1/(4 s^2)

// ---------------------------------------------------------------------------
// warp per row: inv L2 norm + fp16 shadow; spare threads: CSR rowptr + scalars
__global__ void k_invnorm(const float* __restrict__ x,
                          const int*   __restrict__ er,
                          const float* __restrict__ alpha,
                          const float* __restrict__ beta,
                          const float* __restrict__ sigma) {
    int t    = blockIdx.x * blockDim.x + threadIdx.x;
    int row  = t >> 5;
    int lane = t & 31;

    if (t == N_ROWS + 1) {                 // one spare thread: scalars
        float a = expf(alpha[0]);
        float b = expf(beta[0]);
        float s = expf(sigma[0]);
        g_scal[0] = a;
        g_scal[1] = b;
        g_scal[2] = 1.0f / (4.0f * s * s);
    }
    if (t <= N_ROWS) {                     // fused rowptr lower_bound
        int lo = 0, hi = NNZ_E;
        while (lo < hi) {
            int mid = (lo + hi) >> 1;
            if (er[mid] < t) lo = mid + 1; else hi = mid;
        }
        g_rowptr[t] = lo;
    }
    if (row >= N_ROWS) return;

    const float4* xr = (const float4*)(x + (size_t)row * DIM);
    uint4* xh = (uint4*)(g_xh + (size_t)row * DIM);

    float s = 0.0f;
#pragma unroll
    for (int seg = 0; seg < 2; seg++) {
        float4 a = xr[2 * lane + 64 * seg];
        float4 b = xr[2 * lane + 1 + 64 * seg];
        s += a.x * a.x + a.y * a.y + a.z * a.z + a.w * a.w;
        s += b.x * b.x + b.y * b.y + b.z * b.z + b.w * b.w;
        __half2 h0 = __floats2half2_rn(a.x, a.y);
        __half2 h1 = __floats2half2_rn(a.z, a.w);
        __half2 h2 = __floats2half2_rn(b.x, b.y);
        __half2 h3 = __floats2half2_rn(b.z, b.w);
        uint4 u;
        u.x = *(unsigned*)&h0; u.y = *(unsigned*)&h1;
        u.z = *(unsigned*)&h2; u.w = *(unsigned*)&h3;
        xh[lane + 32 * seg] = u;
    }
#pragma unroll
    for (int o = 16; o; o >>= 1) s += __shfl_xor_sync(0xFFFFFFFFu, s, o);
    if (lane == 0) {
        g_invnorm[row] = rsqrtf(fmaxf(s, 1e-12f));
        g_rowsum[row]  = 0.0f;
    }
}

// 8 lanes per edge (4 edges/warp): 16 indep loads in flight per lane.
// launch_bounds(,6) raises occupancy (latency-bound: R7 profile occ=52%, issue=20%).
__global__ void __launch_bounds__(TPB, 6)
k_sup(const float* __restrict__ ev,
      const int*   __restrict__ er,
      const int*   __restrict__ ec) {
    int t = blockIdx.x * blockDim.x + threadIdx.x;
    int e = t >> 3;
    int q = t & 7;
    if (e >= NNZ_E) return;

    int row = er[e];
    int col = ec[e];
    const uint4* xr = (const uint4*)(g_xh + (size_t)row * DIM);
    const uint4* xc = (const uint4*)(g_xh + (size_t)col * DIM);

    __half2 acc0 = __float2half2_rn(0.0f);
    __half2 acc1 = __float2half2_rn(0.0f);
#pragma unroll
    for (int j = 0; j < 8; j += 2) {
        uint4 r0 = xr[q + 8 * j];
        uint4 c0 = xc[q + 8 * j];
        uint4 r1 = xr[q + 8 * (j + 1)];
        uint4 c1 = xc[q + 8 * (j + 1)];
#pragma unroll
        for (int m = 0; m < 4; m++) {
            unsigned ra = (&r0.x)[m], ca = (&c0.x)[m];
            unsigned rb = (&r1.x)[m], cb = (&c1.x)[m];
            acc0 = __hfma2(*(__half2*)&ra, *(__half2*)&ca, acc0);
            acc1 = __hfma2(*(__half2*)&rb, *(__half2*)&cb, acc1);
        }
    }
    float2 f0 = __half22float2(acc0);
    float2 f1 = __half22float2(acc1);
    float d = f0.x + f0.y + f1.x + f1.y;
    d += __shfl_xor_sync(0xFFFFFFFFu, d, 1);
    d += __shfl_xor_sync(0xFFFFFFFFu, d, 2);
    d += __shfl_xor_sync(0xFFFFFFFFu, d, 4);

    if (q == 0) {
        float sim = (col == row) ? 0.0f : d * g_invnorm[row] * g_invnorm[col];
        float sup = ev[e] * expf(sim * g_scal[2]);
        g_cw[e] = make_int2(col, __float_as_int(sup));
        atomicAdd(&g_rowsum[row], sup);
    }
}

// cumulative weight up to (but not including) half-row hr
__device__ __forceinline__ long long cumW(int hr) {
    int r = hr >> 1, h = hr & 1;
    long long edges = 2LL * g_rowptr[r] + (h ? (g_rowptr[r + 1] - g_rowptr[r]) : 0);
    return edges + (long long)W_FIX * hr;
}

// tiny: denom arrays (per row) + balanced warp splits (per warp slot)
__global__ void k_meta() {
    int i = blockIdx.x * blockDim.x + threadIdx.x;
    float a = g_scal[0], b = g_scal[1];

    if (i < N_ROWS) {
        float idn = 1.0f / (b + g_rowsum[i] * a + a);
        g_idn[i]  = idn;
        g_aidn[i] = a * idn;
    }
    if (i <= NWARP) {
        long long W = 2LL * NNZ_E + (long long)W_FIX * HR_TOTAL;
        long long tgt = (long long)i * W / NWARP;
        int lo = 0, hi = HR_TOTAL;
        while (lo < hi) {
            int mid = (lo + hi) >> 1;
            if (cumW(mid) < tgt) lo = mid + 1; else hi = mid;
        }
        g_wsplit[i] = lo;
    }
}

// balanced warps: each warp processes its half-row range for one iteration.
// R11-proven inner loop: 4-edge groups, in-loop offset shift + weight convert,
// packed half2 chain (1 HMUL2 + 3 HFMA2 per word), one fp32 flush per word.
__global__ void __launch_bounds__(TPB, 6)
k_iter(const __half* __restrict__ in_h,
       const float*  __restrict__ x,
       __half*       __restrict__ out_h,
       float*        __restrict__ out_f,
       int first, int last) {
    int gw   = (blockIdx.x * TPB + threadIdx.x) >> 5;
    int lane = threadIdx.x & 31;
    int hr0 = g_wsplit[gw];
    int hr1 = g_wsplit[gw + 1];

    for (int hr = hr0; hr < hr1; hr++) {
        int row = hr >> 1, half = hr & 1;
        int e0 = g_rowptr[row], e1 = g_rowptr[row + 1];
        float aidn = g_aidn[row];
        const __half* base = in_h + half * (DIM / 2);

        float acc[8];
#pragma unroll
        for (int i = 0; i < 8; i++) acc[i] = 0.0f;

        int e = e0;
        for (; e + 3 < e1; e += 4) {
            int2 A = g_cw[e], B = g_cw[e + 1], C = g_cw[e + 2], D = g_cw[e + 3];
            uint4 uA = ((const uint4*)(base + ((size_t)A.x << 9)))[lane];
            uint4 uB = ((const uint4*)(base + ((size_t)B.x << 9)))[lane];
            uint4 uC = ((const uint4*)(base + ((size_t)C.x << 9)))[lane];
            uint4 uD = ((const uint4*)(base + ((size_t)D.x << 9)))[lane];
            __half2 wA = __float2half2_rn(__int_as_float(A.y));
            __half2 wB = __float2half2_rn(__int_as_float(B.y));
            __half2 wC = __float2half2_rn(__int_as_float(C.y));
            __half2 wD = __float2half2_rn(__int_as_float(D.y));
#pragma unroll
            for (int j = 0; j < 4; j++) {
                unsigned ra = (&uA.x)[j], rb = (&uB.x)[j];
                unsigned rc = (&uC.x)[j], rd = (&uD.x)[j];
                __half2 t = __hmul2(wD, *(__half2*)&rd);
                t = __hfma2(wC, *(__half2*)&rc, t);
                t = __hfma2(wB, *(__half2*)&rb, t);
                t = __hfma2(wA, *(__half2*)&ra, t);
                float2 f = __half22float2(t);
                acc[2 * j]     += f.x;
                acc[2 * j + 1] += f.y;
            }
        }
        for (; e < e1; e++) {
            int2 A = g_cw[e];
            float w = __int_as_float(A.y);
            uint4 u = ((const uint4*)(base + ((size_t)A.x << 9)))[lane];
#pragma unroll
            for (int j = 0; j < 4; j++) {
                unsigned raw = (&u.x)[j];
                float2 f = __half22float2(*(__half2*)&raw);
                acc[2 * j]     += w * f.x;
                acc[2 * j + 1] += w * f.y;
            }
        }

        size_t off = ((size_t)row << 9) + half * (DIM / 2);
        uint4 ui = ((const uint4*)(in_h + off))[lane];
        float fi[8];
#pragma unroll
        for (int j = 0; j < 4; j++) {
            unsigned raw = (&ui.x)[j];
            float2 f = __half22float2(*(__half2*)&raw);
            fi[2 * j] = f.x; fi[2 * j + 1] = f.y;
        }

        if (first) {
            // iter 0: fi == xh; forcing term computed inline, persisted to g_cx
            float sc = g_scal[1] * g_idn[row];
            float cx[8], o[8];
#pragma unroll
            for (int j = 0; j < 8; j++) {
                cx[j] = fi[j] * sc;
                o[j]  = cx[j] + (acc[j] + fi[j]) * aidn;
            }
            __half2 c0 = __floats2half2_rn(cx[0], cx[1]);
            __half2 c1 = __floats2half2_rn(cx[2], cx[3]);
            __half2 c2 = __floats2half2_rn(cx[4], cx[5]);
            __half2 c3 = __floats2half2_rn(cx[6], cx[7]);
            uint4 uc;
            uc.x = *(unsigned*)&c0; uc.y = *(unsigned*)&c1;
            uc.z = *(unsigned*)&c2; uc.w = *(unsigned*)&c3;
            ((uint4*)(g_cx + off))[lane] = uc;

            __half2 h0 = __floats2half2_rn(o[0], o[1]);
            __half2 h1 = __floats2half2_rn(o[2], o[3]);
            __half2 h2 = __floats2half2_rn(o[4], o[5]);
            __half2 h3 = __floats2half2_rn(o[6], o[7]);
            uint4 u;
            u.x = *(unsigned*)&h0; u.y = *(unsigned*)&h1;
            u.z = *(unsigned*)&h2; u.w = *(unsigned*)&h3;
            ((uint4*)(out_h + off))[lane] = u;
        } else if (!last) {
            uint4 uc = ((const uint4*)(g_cx + off))[lane];
            float o[8];
#pragma unroll
            for (int j = 0; j < 4; j++) {
                unsigned raw = (&uc.x)[j];
                float2 c = __half22float2(*(__half2*)&raw);
                o[2 * j]     = c.x + (acc[2 * j]     + fi[2 * j])     * aidn;
                o[2 * j + 1] = c.y + (acc[2 * j + 1] + fi[2 * j + 1]) * aidn;
            }
            __half2 h0 = __floats2half2_rn(o[0], o[1]);
            __half2 h1 = __floats2half2_rn(o[2], o[3]);
            __half2 h2 = __floats2half2_rn(o[4], o[5]);
            __half2 h3 = __floats2half2_rn(o[6], o[7]);
            uint4 u;
            u.x = *(unsigned*)&h0; u.y = *(unsigned*)&h1;
            u.z = *(unsigned*)&h2; u.w = *(unsigned*)&h3;
            ((uint4*)(out_h + off))[lane] = u;
        } else {
            float b = g_scal[1];
            float idn = g_idn[row];
            const float4* px = (const float4*)(x + off);
            float4 vx0 = px[2 * lane];
            float4 vx1 = px[2 * lane + 1];
            float4 o0, o1;
            o0.x = vx0.x * b * idn + (acc[0] + fi[0]) * aidn;
            o0.y = vx0.y * b * idn + (acc[1] + fi[1]) * aidn;
            o0.z = vx0.z * b * idn + (acc[2] + fi[2]) * aidn;
            o0.w = vx0.w * b * idn + (acc[3] + fi[3]) * aidn;
            o1.x = vx1.x * b * idn + (acc[4] + fi[4]) * aidn;
            o1.y = vx1.y * b * idn + (acc[5] + fi[5]) * aidn;
            o1.z = vx1.z * b * idn + (acc[6] + fi[6]) * aidn;
            o1.w = vx1.w * b * idn + (acc[7] + fi[7]) * aidn;
            float4* po = (float4*)(out_f + off);
            po[2 * lane]     = o0;
            po[2 * lane + 1] = o1;
        }
    }
}

// ---------------------------------------------------------------------------
extern "C" void kernel_launch(void* const* d_in, const int* in_sizes, int n_in,
                              void* d_out, int out_size) {
    const float* x     = (const float*)d_in[0];
    const float* alpha = (const float*)d_in[1];
    const float* beta  = (const float*)d_in[2];
    const float* sigma = (const float*)d_in[3];
    const float* ev    = (const float*)d_in[4];
    const int*   er    = (const int*)d_in[5];
    const int*   ec    = (const int*)d_in[6];
    float*       out   = (float*)d_out;

    __half *h0, *h1, *xh;
    cudaGetSymbolAddress((void**)&h0, g_h0);
    cudaGetSymbolAddress((void**)&h1, g_h1);
    cudaGetSymbolAddress((void**)&xh, g_xh);

    const int ROW_BLOCKS  = (N_ROWS * 32) / TPB;      // warp per row
    const int SUP_BLOCKS  = (NNZ_E * 8) / TPB;        // 8 threads per edge
    const int META_BLOCKS = (N_ROWS + TPB - 1) / TPB;

    k_invnorm<<<ROW_BLOCKS, TPB>>>(x, er, alpha, beta, sigma);
    k_sup<<<SUP_BLOCKS, TPB>>>(ev, er, ec);
    k_meta<<<META_BLOCKS, TPB>>>();

    const __half* in_h = xh;
    for (int it = 0; it < ITERS; it++) {
        int first = (it == 0);
        int last  = (it == ITERS - 1);
        __half* out_h = (it & 1) == 0 ? h0 : h1;
        k_iter<<<NBLK, TPB>>>(in_h, x, out_h, out, first, last);
        in_h = out_h;
    }
}

// round 15
// speedup vs baseline: 1.1300x; 1.0204x over previous
#include <cuda_runtime.h>
#include <cuda_fp16.h>

#define N_ROWS 16384
#define DIM    512
#define NNZ_E  163840
#define ITERS  10

#define NBLK   888                 // single wave at 6 blocks/SM x 148 SMs
#define TPB    256
#define NWARP  (NBLK * 8)          // 7104 worker warps
#define HR_TOTAL (N_ROWS * 2)      // 32768 half-rows
#define W_FIX  3                   // fixed weight per half-row

// Scratch (static __device__ arrays — allocation-free per harness rules)
__device__ __align__(16) __half g_h0[N_ROWS * DIM];
__device__ __align__(16) __half g_h1[N_ROWS * DIM];
__device__ __align__(16) __half g_xh[N_ROWS * DIM];   // fp16 shadow of x
__device__ __align__(16) __half g_cx[N_ROWS * DIM];   // fp16 x*b*invdenom (written by iter 0)
__device__ int2  g_cw[NNZ_E];          // (col, weight-as-int) per edge
__device__ int   g_rowptr[N_ROWS + 1];
__device__ int   g_wsplit[NWARP + 1];  // balanced half-row ranges per warp
__device__ float g_invnorm[N_ROWS];
__device__ float g_rowsum[N_ROWS];
__device__ float g_aidn[N_ROWS];
__device__ float g_idn[N_ROWS];
__device__ float g_scal[3];            // a, b, k = 1/(4 s^2)

// ---------------------------------------------------------------------------
// warp per row: inv L2 norm + fp16 shadow; spare threads: CSR rowptr + scalars
__global__ void k_invnorm(const float* __restrict__ x,
                          const int*   __restrict__ er,
                          const float* __restrict__ alpha,
                          const float* __restrict__ beta,
                          const float* __restrict__ sigma) {
    int t    = blockIdx.x * blockDim.x + threadIdx.x;
    int row  = t >> 5;
    int lane = t & 31;

    if (t == N_ROWS + 1) {                 // one spare thread: scalars
        float a = expf(alpha[0]);
        float b = expf(beta[0]);
        float s = expf(sigma[0]);
        g_scal[0] = a;
        g_scal[1] = b;
        g_scal[2] = 1.0f / (4.0f * s * s);
    }
    if (t <= N_ROWS) {                     // fused rowptr lower_bound
        int lo = 0, hi = NNZ_E;
        while (lo < hi) {
            int mid = (lo + hi) >> 1;
            if (er[mid] < t) lo = mid + 1; else hi = mid;
        }
        g_rowptr[t] = lo;
    }
    if (row >= N_ROWS) return;

    const float4* xr = (const float4*)(x + (size_t)row * DIM);
    uint4* xh = (uint4*)(g_xh + (size_t)row * DIM);

    float s = 0.0f;
#pragma unroll
    for (int seg = 0; seg < 2; seg++) {
        float4 a = xr[2 * lane + 64 * seg];
        float4 b = xr[2 * lane + 1 + 64 * seg];
        s += a.x * a.x + a.y * a.y + a.z * a.z + a.w * a.w;
        s += b.x * b.x + b.y * b.y + b.z * b.z + b.w * b.w;
        __half2 h0 = __floats2half2_rn(a.x, a.y);
        __half2 h1 = __floats2half2_rn(a.z, a.w);
        __half2 h2 = __floats2half2_rn(b.x, b.y);
        __half2 h3 = __floats2half2_rn(b.z, b.w);
        uint4 u;
        u.x = *(unsigned*)&h0; u.y = *(unsigned*)&h1;
        u.z = *(unsigned*)&h2; u.w = *(unsigned*)&h3;
        xh[lane + 32 * seg] = u;
    }
#pragma unroll
    for (int o = 16; o; o >>= 1) s += __shfl_xor_sync(0xFFFFFFFFu, s, o);
    if (lane == 0) {
        g_invnorm[row] = rsqrtf(fmaxf(s, 1e-12f));
        g_rowsum[row]  = 0.0f;
    }
}

// 8 lanes per edge (4 edges/warp): 16 indep loads in flight per lane.
__global__ void __launch_bounds__(TPB, 6)
k_sup(const float* __restrict__ ev,
      const int*   __restrict__ er,
      const int*   __restrict__ ec) {
    int t = blockIdx.x * blockDim.x + threadIdx.x;
    int e = t >> 3;
    int q = t & 7;
    if (e >= NNZ_E) return;

    int row = er[e];
    int col = ec[e];
    const uint4* xr = (const uint4*)(g_xh + (size_t)row * DIM);
    const uint4* xc = (const uint4*)(g_xh + (size_t)col * DIM);

    __half2 acc0 = __float2half2_rn(0.0f);
    __half2 acc1 = __float2half2_rn(0.0f);
#pragma unroll
    for (int j = 0; j < 8; j += 2) {
        uint4 r0 = xr[q + 8 * j];
        uint4 c0 = xc[q + 8 * j];
        uint4 r1 = xr[q + 8 * (j + 1)];
        uint4 c1 = xc[q + 8 * (j + 1)];
#pragma unroll
        for (int m = 0; m < 4; m++) {
            unsigned ra = (&r0.x)[m], ca = (&c0.x)[m];
            unsigned rb = (&r1.x)[m], cb = (&c1.x)[m];
            acc0 = __hfma2(*(__half2*)&ra, *(__half2*)&ca, acc0);
            acc1 = __hfma2(*(__half2*)&rb, *(__half2*)&cb, acc1);
        }
    }
    float2 f0 = __half22float2(acc0);
    float2 f1 = __half22float2(acc1);
    float d = f0.x + f0.y + f1.x + f1.y;
    d += __shfl_xor_sync(0xFFFFFFFFu, d, 1);
    d += __shfl_xor_sync(0xFFFFFFFFu, d, 2);
    d += __shfl_xor_sync(0xFFFFFFFFu, d, 4);

    if (q == 0) {
        float sim = (col == row) ? 0.0f : d * g_invnorm[row] * g_invnorm[col];
        float sup = ev[e] * expf(sim * g_scal[2]);
        g_cw[e] = make_int2(col, __float_as_int(sup));
        atomicAdd(&g_rowsum[row], sup);
    }
}

// cumulative weight up to (but not including) half-row hr
__device__ __forceinline__ long long cumW(int hr) {
    int r = hr >> 1, h = hr & 1;
    long long edges = 2LL * g_rowptr[r] + (h ? (g_rowptr[r + 1] - g_rowptr[r]) : 0);
    return edges + (long long)W_FIX * hr;
}

// tiny: denom arrays (per row) + balanced warp splits (per warp slot)
__global__ void k_meta() {
    int i = blockIdx.x * blockDim.x + threadIdx.x;
    float a = g_scal[0], b = g_scal[1];

    if (i < N_ROWS) {
        float idn = 1.0f / (b + g_rowsum[i] * a + a);
        g_idn[i]  = idn;
        g_aidn[i] = a * idn;
    }
    if (i <= NWARP) {
        long long W = 2LL * NNZ_E + (long long)W_FIX * HR_TOTAL;
        long long tgt = (long long)i * W / NWARP;
        int lo = 0, hi = HR_TOTAL;
        while (lo < hi) {
            int mid = (lo + hi) >> 1;
            if (cumW(mid) < tgt) lo = mid + 1; else hi = mid;
        }
        g_wsplit[i] = lo;
    }
}

// R11-proven gather loop: 4-edge groups, in-loop shift + weight convert,
// packed half2 chain, fp32 flush per word. DO NOT TOUCH (R12/R13 regressed).
__device__ __forceinline__ void gather_row(const __half* __restrict__ base,
                                           int e0, int e1, int lane,
                                           float* __restrict__ acc) {
#pragma unroll
    for (int i = 0; i < 8; i++) acc[i] = 0.0f;

    int e = e0;
    for (; e + 3 < e1; e += 4) {
        int2 A = g_cw[e], B = g_cw[e + 1], C = g_cw[e + 2], D = g_cw[e + 3];
        uint4 uA = ((const uint4*)(base + ((size_t)A.x << 9)))[lane];
        uint4 uB = ((const uint4*)(base + ((size_t)B.x << 9)))[lane];
        uint4 uC = ((const uint4*)(base + ((size_t)C.x << 9)))[lane];
        uint4 uD = ((const uint4*)(base + ((size_t)D.x << 9)))[lane];
        __half2 wA = __float2half2_rn(__int_as_float(A.y));
        __half2 wB = __float2half2_rn(__int_as_float(B.y));
        __half2 wC = __float2half2_rn(__int_as_float(C.y));
        __half2 wD = __float2half2_rn(__int_as_float(D.y));
#pragma unroll
        for (int j = 0; j < 4; j++) {
            unsigned ra = (&uA.x)[j], rb = (&uB.x)[j];
            unsigned rc = (&uC.x)[j], rd = (&uD.x)[j];
            __half2 t = __hmul2(wD, *(__half2*)&rd);
            t = __hfma2(wC, *(__half2*)&rc, t);
            t = __hfma2(wB, *(__half2*)&rb, t);
            t = __hfma2(wA, *(__half2*)&ra, t);
            float2 f = __half22float2(t);
            acc[2 * j]     += f.x;
            acc[2 * j + 1] += f.y;
        }
    }
    for (; e < e1; e++) {
        int2 A = g_cw[e];
        float w = __int_as_float(A.y);
        uint4 u = ((const uint4*)(base + ((size_t)A.x << 9)))[lane];
#pragma unroll
        for (int j = 0; j < 4; j++) {
            unsigned raw = (&u.x)[j];
            float2 f = __half22float2(*(__half2*)&raw);
            acc[2 * j]     += w * f.x;
            acc[2 * j + 1] += w * f.y;
        }
    }
}

__device__ __forceinline__ uint4 pack8h(const float* o) {
    __half2 h0 = __floats2half2_rn(o[0], o[1]);
    __half2 h1 = __floats2half2_rn(o[2], o[3]);
    __half2 h2 = __floats2half2_rn(o[4], o[5]);
    __half2 h3 = __floats2half2_rn(o[6], o[7]);
    uint4 u;
    u.x = *(unsigned*)&h0; u.y = *(unsigned*)&h1;
    u.z = *(unsigned*)&h2; u.w = *(unsigned*)&h3;
    return u;
}

// iter 0: in = g_xh; computes forcing inline and persists it to g_cx
__global__ void __launch_bounds__(TPB, 6)
k_iter_first(__half* __restrict__ out_h) {
    int gw   = (blockIdx.x * TPB + threadIdx.x) >> 5;
    int lane = threadIdx.x & 31;
    int hr1 = g_wsplit[gw + 1];

    for (int hr = g_wsplit[gw]; hr < hr1; hr++) {
        int row = hr >> 1, half = hr & 1;
        float aidn = g_aidn[row];
        const __half* base = g_xh + half * (DIM / 2);

        float acc[8];
        gather_row(base, g_rowptr[row], g_rowptr[row + 1], lane, acc);

        size_t off = ((size_t)row << 9) + half * (DIM / 2);
        uint4 ui = ((const uint4*)(g_xh + off))[lane];
        float sc = g_scal[1] * g_idn[row];
        float cx[8], o[8];
#pragma unroll
        for (int j = 0; j < 4; j++) {
            unsigned raw = (&ui.x)[j];
            float2 f = __half22float2(*(__half2*)&raw);
            cx[2 * j]     = f.x * sc;
            cx[2 * j + 1] = f.y * sc;
            o[2 * j]      = cx[2 * j]     + (acc[2 * j]     + f.x) * aidn;
            o[2 * j + 1]  = cx[2 * j + 1] + (acc[2 * j + 1] + f.y) * aidn;
        }
        ((uint4*)(g_cx + off))[lane]  = pack8h(cx);
        ((uint4*)(out_h + off))[lane] = pack8h(o);
    }
}

// iters 1..8: forcing from g_cx, fp16 in/out
__global__ void __launch_bounds__(TPB, 6)
k_iter_mid(const __half* __restrict__ in_h,
           __half*       __restrict__ out_h) {
    int gw   = (blockIdx.x * TPB + threadIdx.x) >> 5;
    int lane = threadIdx.x & 31;
    int hr1 = g_wsplit[gw + 1];

    for (int hr = g_wsplit[gw]; hr < hr1; hr++) {
        int row = hr >> 1, half = hr & 1;
        float aidn = g_aidn[row];
        const __half* base = in_h + half * (DIM / 2);

        float acc[8];
        gather_row(base, g_rowptr[row], g_rowptr[row + 1], lane, acc);

        size_t off = ((size_t)row << 9) + half * (DIM / 2);
        uint4 ui = ((const uint4*)(in_h + off))[lane];
        uint4 uc = ((const uint4*)(g_cx + off))[lane];
        float o[8];
#pragma unroll
        for (int j = 0; j < 4; j++) {
            unsigned ri = (&ui.x)[j], rc = (&uc.x)[j];
            float2 f = __half22float2(*(__half2*)&ri);
            float2 c = __half22float2(*(__half2*)&rc);
            o[2 * j]     = c.x + (acc[2 * j]     + f.x) * aidn;
            o[2 * j + 1] = c.y + (acc[2 * j + 1] + f.y) * aidn;
        }
        ((uint4*)(out_h + off))[lane] = pack8h(o);
    }
}

// iter 9: forcing from g_cx, fp32 output only
__global__ void __launch_bounds__(TPB, 6)
k_iter_last(const __half* __restrict__ in_h,
            float*        __restrict__ out_f) {
    int gw   = (blockIdx.x * TPB + threadIdx.x) >> 5;
    int lane = threadIdx.x & 31;
    int hr1 = g_wsplit[gw + 1];

    for (int hr = g_wsplit[gw]; hr < hr1; hr++) {
        int row = hr >> 1, half = hr & 1;
        float aidn = g_aidn[row];
        const __half* base = in_h + half * (DIM / 2);

        float acc[8];
        gather_row(base, g_rowptr[row], g_rowptr[row + 1], lane, acc);

        size_t off = ((size_t)row << 9) + half * (DIM / 2);
        uint4 ui = ((const uint4*)(in_h + off))[lane];
        uint4 uc = ((const uint4*)(g_cx + off))[lane];
        float4 o0, o1;
        {
            unsigned ri = ui.x, rc = uc.x;
            float2 f = __half22float2(*(__half2*)&ri);
            float2 c = __half22float2(*(__half2*)&rc);
            o0.x = c.x + (acc[0] + f.x) * aidn;
            o0.y = c.y + (acc[1] + f.y) * aidn;
        }
        {
            unsigned ri = ui.y, rc = uc.y;
            float2 f = __half22float2(*(__half2*)&ri);
            float2 c = __half22float2(*(__half2*)&rc);
            o0.z = c.x + (acc[2] + f.x) * aidn;
            o0.w = c.y + (acc[3] + f.y) * aidn;
        }
        {
            unsigned ri = ui.z, rc = uc.z;
            float2 f = __half22float2(*(__half2*)&ri);
            float2 c = __half22float2(*(__half2*)&rc);
            o1.x = c.x + (acc[4] + f.x) * aidn;
            o1.y = c.y + (acc[5] + f.y) * aidn;
        }
        {
            unsigned ri = ui.w, rc = uc.w;
            float2 f = __half22float2(*(__half2*)&ri);
            float2 c = __half22float2(*(__half2*)&rc);
            o1.z = c.x + (acc[6] + f.x) * aidn;
            o1.w = c.y + (acc[7] + f.y) * aidn;
        }
        float4* po = (float4*)(out_f + off);
        po[2 * lane]     = o0;
        po[2 * lane + 1] = o1;
    }
}

// ---------------------------------------------------------------------------
extern "C" void kernel_launch(void* const* d_in, const int* in_sizes, int n_in,
                              void* d_out, int out_size) {
    const float* x     = (const float*)d_in[0];
    const float* alpha = (const float*)d_in[1];
    const float* beta  = (const float*)d_in[2];
    const float* sigma = (const float*)d_in[3];
    const float* ev    = (const float*)d_in[4];
    const int*   er    = (const int*)d_in[5];
    const int*   ec    = (const int*)d_in[6];
    float*       out   = (float*)d_out;

    __half *h0, *h1;
    cudaGetSymbolAddress((void**)&h0, g_h0);
    cudaGetSymbolAddress((void**)&h1, g_h1);

    const int ROW_BLOCKS  = (N_ROWS * 32) / TPB;      // warp per row
    const int SUP_BLOCKS  = (NNZ_E * 8) / TPB;        // 8 threads per edge
    const int META_BLOCKS = (N_ROWS + TPB - 1) / TPB;

    k_invnorm<<<ROW_BLOCKS, TPB>>>(x, er, alpha, beta, sigma);
    k_sup<<<SUP_BLOCKS, TPB>>>(ev, er, ec);
    k_meta<<<META_BLOCKS, TPB>>>();

    k_iter_first<<<NBLK, TPB>>>(h0);                  // iter 0 (in = g_xh)
    const __half* in_h = h0;
    for (int it = 1; it < ITERS - 1; it++) {          // iters 1..8
        __half* out_h = (it & 1) == 0 ? h0 : h1;
        k_iter_mid<<<NBLK, TPB>>>(in_h, out_h);
        in_h = out_h;
    }
    k_iter_last<<<NBLK, TPB>>>(in_h, out);            // iter 9
}